// round 14
// baseline (speedup 1.0000x reference)
#include <cuda_runtime.h>
#include <cstdint>
#include <math.h>

// ---------------- problem constants ----------------
constexpr int BATCH = 2;
constexpr int H     = 16;
constexpr int L     = 2048;
constexpr int D     = 64;
constexpr int C     = 1024;
constexpr long Y_ELEMS = (long)BATCH * L * C;
constexpr float QK_SCALE = 0.022097086912079608f;   // 1/sqrt(2048)

#define SST 36   // single-buffer core (pv): row stride, conflict-free
#define ST2 20   // double-buffer core: BK=16 + 4 pad, conflict-free & 16B-aligned

// ---------------- scratch ----------------
__device__ float g_qh[(long)BATCH * H * L * D];   // [bh][l][d]
__device__ float g_kh[(long)BATCH * H * L * D];   // [bh][l][d]
__device__ float g_vt[(long)BATCH * H * D * L];   // [bh][d][l]  (V transposed)
__device__ float g_yh[(long)BATCH * L * H * D];   // [b][l][h*64+d]
__device__ float g_Z[BATCH * H * L];
__device__ float g_invZ[BATCH * H * L];

// ---------------- helpers ----------------
__device__ __forceinline__ uint32_t smem_u32(const void* p) {
    uint32_t a;
    asm("{ .reg .u64 t; cvta.to.shared.u64 t, %1; cvt.u32.u64 %0, t; }" : "=r"(a) : "l"(p));
    return a;
}
__device__ __forceinline__ uint32_t f2tf(float f) {
    uint32_t r;
    asm("cvt.rna.tf32.f32 %0, %1;" : "=r"(r) : "f"(f));
    return r;
}
__device__ __forceinline__ void mma8(float* c, const uint32_t* a, const uint32_t* b) {
    asm volatile("mma.sync.aligned.m16n8k8.row.col.f32.tf32.tf32.f32 "
        "{%0,%1,%2,%3}, {%4,%5,%6,%7}, {%8,%9}, {%0,%1,%2,%3};"
        : "+f"(c[0]), "+f"(c[1]), "+f"(c[2]), "+f"(c[3])
        : "r"(a[0]), "r"(a[1]), "r"(a[2]), "r"(a[3]), "r"(b[0]), "r"(b[1]));
}
// ldmatrix x4: four 8x8 b16 tiles == four 8x4 tf32 tiles (bit-identical layout)
__device__ __forceinline__ void ldm4(uint32_t* r, uint32_t saddr) {
    asm volatile("ldmatrix.sync.aligned.m8n8.x4.shared.b16 {%0,%1,%2,%3}, [%4];"
        : "=r"(r[0]), "=r"(r[1]), "=r"(r[2]), "=r"(r[3]) : "r"(saddr));
}

// ---------------- GEMM core v10: double-buffered smem, BK=16, ldmatrix ----------------
// D[BM x BN] = A[BM x K] * B[BN x K]^T, fp32 gmem (K contiguous), tf32 MMA.
// 128 threads = 4 warps, warp tile 64x64, warp grid WM x (4/WM). Two smem stages;
// per-iter: LDG(it+1)->regs, MMA(it) via ldmatrix, STS(it+1 -> other stage), ONE sync.
// LDG latency hides under the MMA block; staging is only (BM+BN)/32 float4 regs.
// acc[mt][nt][4]: row = wm+mt*16+group (+8), col = wn+nt*8+tig*2 (+1).
template<int BM, int BN, int WM>
__device__ __forceinline__ void gemm10(const float* __restrict__ A, long lda,
                                       const float* __restrict__ Bp, long ldb,
                                       int niter, float acc[4][8][4],
                                       uint32_t* __restrict__ sm) {
    constexpr int S1 = (BM + BN) * ST2;           // words per stage
    constexpr int NA = BM / 32, NB = BN / 32;     // float4 per thread
    const int tid = threadIdx.x, lane = tid & 31, wid = tid >> 5;
    const int wm = (wid % WM) * 64, wn = (wid / WM) * 64;

    const uint32_t base = smem_u32(sm);
    uint32_t aAdr[4], bAdr[4];
    {
        const int arow = lane & 15, akadd = (lane >> 4) * 4;
        #pragma unroll
        for (int mt = 0; mt < 4; mt++)
            aAdr[mt] = base + (uint32_t)(((wm + mt * 16 + arow) * ST2 + akadd) * 4);
        const int brow = ((lane >> 4) & 1) * 8 + (lane & 7);
        const int bkadd = ((lane >> 3) & 1) * 4;
        #pragma unroll
        for (int p = 0; p < 4; p++)
            bAdr[p] = base + (uint32_t)((BM * ST2 + (wn + p * 16 + brow) * ST2 + bkadd) * 4);
    }

    float4 av[NA], bv[NB];
    // prologue: stage 0
    #pragma unroll
    for (int i = 0; i < NA; i++) {
        int c = tid + i * 128, r = c >> 2, q = (c & 3) * 4;
        av[i] = *(const float4*)(A + (long)r * lda + q);
    }
    #pragma unroll
    for (int i = 0; i < NB; i++) {
        int c = tid + i * 128, r = c >> 2, q = (c & 3) * 4;
        bv[i] = *(const float4*)(Bp + (long)r * ldb + q);
    }
    #pragma unroll
    for (int i = 0; i < NA; i++) {
        int c = tid + i * 128, r = c >> 2, q = (c & 3) * 4;
        *(uint4*)&sm[r * ST2 + q] =
            make_uint4(f2tf(av[i].x), f2tf(av[i].y), f2tf(av[i].z), f2tf(av[i].w));
    }
    #pragma unroll
    for (int i = 0; i < NB; i++) {
        int c = tid + i * 128, r = c >> 2, q = (c & 3) * 4;
        *(uint4*)&sm[BM * ST2 + r * ST2 + q] =
            make_uint4(f2tf(bv[i].x), f2tf(bv[i].y), f2tf(bv[i].z), f2tf(bv[i].w));
    }
    __syncthreads();

    for (int it = 0; it < niter; it++) {
        const uint32_t off = (uint32_t)((it & 1) * S1 * 4);
        const bool more = (it + 1 < niter);
        if (more) {   // prefetch next stage into registers (overlaps MMA below)
            const long k0 = (long)(it + 1) * 16;
            #pragma unroll
            for (int i = 0; i < NA; i++) {
                int c = tid + i * 128, r = c >> 2, q = (c & 3) * 4;
                av[i] = *(const float4*)(A + (long)r * lda + k0 + q);
            }
            #pragma unroll
            for (int i = 0; i < NB; i++) {
                int c = tid + i * 128, r = c >> 2, q = (c & 3) * 4;
                bv[i] = *(const float4*)(Bp + (long)r * ldb + k0 + q);
            }
        }

        #pragma unroll
        for (int ks = 0; ks < 2; ks++) {
            uint32_t af[4][4], bf[4][4];
            #pragma unroll
            for (int mt = 0; mt < 4; mt++) ldm4(af[mt], aAdr[mt] + off + ks * 32);
            #pragma unroll
            for (int p = 0; p < 4; p++) ldm4(bf[p], bAdr[p] + off + ks * 32);
            #pragma unroll
            for (int mt = 0; mt < 4; mt++)
                #pragma unroll
                for (int p = 0; p < 4; p++) {
                    mma8(acc[mt][2 * p],     af[mt], &bf[p][0]);
                    mma8(acc[mt][2 * p + 1], af[mt], &bf[p][2]);
                }
        }

        if (more) {   // store next stage into the OTHER buffer (no extra sync needed)
            uint32_t* dst = sm + ((it + 1) & 1) * S1;
            #pragma unroll
            for (int i = 0; i < NA; i++) {
                int c = tid + i * 128, r = c >> 2, q = (c & 3) * 4;
                *(uint4*)&dst[r * ST2 + q] =
                    make_uint4(f2tf(av[i].x), f2tf(av[i].y), f2tf(av[i].z), f2tf(av[i].w));
            }
            #pragma unroll
            for (int i = 0; i < NB; i++) {
                int c = tid + i * 128, r = c >> 2, q = (c & 3) * 4;
                *(uint4*)&dst[BM * ST2 + r * ST2 + q] =
                    make_uint4(f2tf(bv[i].x), f2tf(bv[i].y), f2tf(bv[i].z), f2tf(bv[i].w));
            }
        }
        __syncthreads();
    }
}

// ---------------- GEMM core v9 (pv only, proven): single-buffer BK=32 + WB ----------------
template<int BM_, int BN_, int WM_, bool WB>
__device__ __forceinline__ void gemm9(const float* __restrict__ A, long lda,
                                      const float* __restrict__ Bp, long ldb,
                                      int niter, float acc[4][8][4],
                                      uint32_t* __restrict__ As, uint32_t* __restrict__ Bs,
                                      float* __restrict__ wb_out, long wb_ld,
                                      const float* __restrict__ invz) {
    constexpr int NA = BM_ / 16, NB = BN_ / 16;
    const int tid = threadIdx.x;
    const int lane = tid & 31, wid = tid >> 5;
    const int wm = (wid % WM_) * 64, wn = (wid / WM_) * 64;

    const uint32_t aB = smem_u32(As), bB = smem_u32(Bs);
    uint32_t aAdr[4], bAdr[4];
    {
        const int arow = lane & 15, akadd = (lane >> 4) * 4;
        #pragma unroll
        for (int mt = 0; mt < 4; mt++)
            aAdr[mt] = aB + (uint32_t)(((wm + mt * 16 + arow) * SST + akadd) * 4);
        const int brow = ((lane >> 4) & 1) * 8 + (lane & 7);
        const int bkadd = ((lane >> 3) & 1) * 4;
        #pragma unroll
        for (int p = 0; p < 4; p++)
            bAdr[p] = bB + (uint32_t)(((wn + p * 16 + brow) * SST + bkadd) * 4);
    }

    for (int it = 0; it < niter; it++) {
        const long k0 = (long)it * 32;
        float4 av[NA], bv[NB];
        #pragma unroll
        for (int i = 0; i < NA; i++) {
            int c = tid + i * 128, r = c >> 3, q = (c & 7) * 4;
            av[i] = *(const float4*)(A + (long)r * lda + k0 + q);
        }
        #pragma unroll
        for (int i = 0; i < NB; i++) {
            int c = tid + i * 128, r = c >> 3, q = (c & 7) * 4;
            bv[i] = *(const float4*)(Bp + (long)r * ldb + k0 + q);
        }
        __syncthreads();
        #pragma unroll
        for (int i = 0; i < NA; i++) {
            int c = tid + i * 128, r = c >> 3, q = (c & 7) * 4;
            *(uint4*)&As[r * SST + q] =
                make_uint4(f2tf(av[i].x), f2tf(av[i].y), f2tf(av[i].z), f2tf(av[i].w));
        }
        #pragma unroll
        for (int i = 0; i < NB; i++) {
            int c = tid + i * 128, r = c >> 3, q = (c & 7) * 4;
            *(uint4*)&Bs[r * SST + q] =
                make_uint4(f2tf(bv[i].x), f2tf(bv[i].y), f2tf(bv[i].z), f2tf(bv[i].w));
        }
        __syncthreads();

        #pragma unroll
        for (int ks = 0; ks < 4; ks++) {
            uint32_t af[4][4], bf[4][4];
            #pragma unroll
            for (int mt = 0; mt < 4; mt++) ldm4(af[mt], aAdr[mt] + ks * 32);
            #pragma unroll
            for (int p = 0; p < 4; p++) ldm4(bf[p], bAdr[p] + ks * 32);
            #pragma unroll
            for (int mt = 0; mt < 4; mt++)
                #pragma unroll
                for (int p = 0; p < 4; p++) {
                    mma8(acc[mt][2 * p],     af[mt], &bf[p][0]);
                    mma8(acc[mt][2 * p + 1], af[mt], &bf[p][2]);
                }
        }

        if (WB) {   // fused normalization writeback of the consumed A chunk
            #pragma unroll
            for (int i = 0; i < NA; i++) {
                int c = tid + i * 128, r = c >> 3, q = (c & 7) * 4;
                const uint32_t* p = &As[r * SST + q];
                const float s = invz[r];
                *(float4*)(wb_out + (long)r * wb_ld + k0 + q) =
                    make_float4(__uint_as_float(p[0]) * s, __uint_as_float(p[1]) * s,
                                __uint_as_float(p[2]) * s, __uint_as_float(p[3]) * s);
            }
        }
    }
}

// ---------------- kernels ----------------
// merged projections: z=0 -> qh, z=1 -> kh, z=2 -> vt (transposed)
__global__ void __launch_bounds__(128) proj_kernel(const float* __restrict__ q,
                                                   const float* __restrict__ k,
                                                   const float* __restrict__ v,
                                                   const float* __restrict__ wq,
                                                   const float* __restrict__ wk,
                                                   const float* __restrict__ wv) {
    __shared__ uint32_t sm[2 * (128 + 128) * ST2];
    const int which = blockIdx.z;
    const float* X = (which == 0) ? q : (which == 1) ? k : v;
    const float* W = (which == 0) ? wq : (which == 1) ? wk : wv;

    float acc[4][8][4] = {};
    const int m0 = blockIdx.y * 128, n0 = blockIdx.x * 128;
    gemm10<128, 128, 2>(X + (long)m0 * C, C, W + (long)n0 * C, C, C / 16, acc, sm);

    const int lane = threadIdx.x & 31, wid = threadIdx.x >> 5;
    const int wm = (wid % 2) * 64, wn = (wid / 2) * 64;
    const int group = lane >> 2, tig = lane & 3;
    #pragma unroll
    for (int mt = 0; mt < 4; mt++)
        #pragma unroll
        for (int half = 0; half < 2; half++) {
            const int m = m0 + wm + mt * 16 + group + 8 * half;
            const int b = m >> 11, l = m & 2047;
            if (which == 2) {
                #pragma unroll
                for (int nt = 0; nt < 8; nt++) {
                    const int n = n0 + wn + nt * 8 + tig * 2;
                    const int h = n >> 6, d = n & 63;
                    float* out = g_vt + (long)(b * H + h) * D * L;
                    out[(long)d * L + l]       = acc[mt][nt][2 * half];
                    out[(long)(d + 1) * L + l] = acc[mt][nt][2 * half + 1];
                }
            } else {
                float* base = (which == 0) ? g_qh : g_kh;
                #pragma unroll
                for (int nt = 0; nt < 8; nt++) {
                    const int n = n0 + wn + nt * 8 + tig * 2;
                    const int h = n >> 6, d = n & 63;
                    *(float2*)(base + ((long)(b * H + h) * L + l) * D + d) =
                        make_float2(acc[mt][nt][2 * half], acc[mt][nt][2 * half + 1]);
                }
            }
        }
}

// QK^T -> exp -> unnormalized attn + row-sum atomics
__global__ void __launch_bounds__(128) qk_kernel(float* __restrict__ attnU) {
    __shared__ uint32_t sm[2 * (128 + 128) * ST2];
    float acc[4][8][4] = {};
    const int n0 = blockIdx.x * 128, m0 = blockIdx.y * 128, bh = blockIdx.z;
    gemm10<128, 128, 2>(g_qh + ((long)bh * L + m0) * D, D,
                        g_kh + ((long)bh * L + n0) * D, D, D / 16, acc, sm);

    const int lane = threadIdx.x & 31, wid = threadIdx.x >> 5;
    const int wm = (wid % 2) * 64, wn = (wid / 2) * 64;
    const int group = lane >> 2, tig = lane & 3;
    float* outbase = attnU + (long)bh * L * L;
    #pragma unroll
    for (int mt = 0; mt < 4; mt++)
        #pragma unroll
        for (int half = 0; half < 2; half++) {
            const int row = m0 + wm + mt * 16 + group + 8 * half;
            float* outr = outbase + (long)row * L + n0 + wn;
            float sum = 0.0f;
            #pragma unroll
            for (int nt = 0; nt < 8; nt++) {
                float e0 = __expf(acc[mt][nt][2 * half] * QK_SCALE);
                float e1 = __expf(acc[mt][nt][2 * half + 1] * QK_SCALE);
                sum += e0 + e1;
                *(float2*)(outr + nt * 8 + tig * 2) = make_float2(e0, e1);
            }
            sum += __shfl_xor_sync(0xFFFFFFFF, sum, 1);
            sum += __shfl_xor_sync(0xFFFFFFFF, sum, 2);
            if (tig == 0) atomicAdd(&g_Z[bh * L + row], sum);
        }
}

// PV with fused normalization: reads unnormalized attn, writes normalized attn
// in place + scaled yh.
__global__ void __launch_bounds__(128) pv_kernel(float* __restrict__ attn) {
    __shared__ uint32_t As[256 * SST], Bs[64 * SST];
    __shared__ float invz_s[256];
    const int m0 = blockIdx.x * 256, bh = blockIdx.y;
    for (int i = threadIdx.x; i < 256; i += 128)
        invz_s[i] = g_invZ[bh * L + m0 + i];
    __syncthreads();

    float acc[4][8][4] = {};
    float* arow = attn + (long)bh * L * L + (long)m0 * L;
    gemm9<256, 64, 4, true>(arow, L, g_vt + (long)bh * D * L, L, L / 32, acc,
                            As, Bs, arow, L, invz_s);

    const int lane = threadIdx.x & 31, wid = threadIdx.x >> 5;
    const int wm = wid * 64;
    const int group = lane >> 2, tig = lane & 3;
    const int b = bh >> 4, hh = bh & 15;
    #pragma unroll
    for (int mt = 0; mt < 4; mt++)
        #pragma unroll
        for (int half = 0; half < 2; half++) {
            const int rl = wm + mt * 16 + group + 8 * half;
            const float s = invz_s[rl];
            float* out = g_yh + (long)(b * L + m0 + rl) * C + hh * 64;
            #pragma unroll
            for (int nt = 0; nt < 8; nt++)
                *(float2*)(out + nt * 8 + tig * 2) =
                    make_float2(acc[mt][nt][2 * half] * s, acc[mt][nt][2 * half + 1] * s);
        }
}

// y = yh @ fc_y^T
__global__ void __launch_bounds__(128) final_kernel(const float* __restrict__ Wf,
                                                    float* __restrict__ Y) {
    __shared__ uint32_t sm[2 * (128 + 128) * ST2];
    float acc[4][8][4] = {};
    const int n0 = blockIdx.x * 128, m0 = blockIdx.y * 128;
    gemm10<128, 128, 2>(g_yh + (long)m0 * C, C, Wf + (long)n0 * C, C, C / 16, acc, sm);

    const int lane = threadIdx.x & 31, wid = threadIdx.x >> 5;
    const int wm = (wid % 2) * 64, wn = (wid / 2) * 64;
    const int group = lane >> 2, tig = lane & 3;
    #pragma unroll
    for (int mt = 0; mt < 4; mt++)
        #pragma unroll
        for (int half = 0; half < 2; half++) {
            const int row = m0 + wm + mt * 16 + group + 8 * half;
            float* out = Y + (long)row * C + n0 + wn;
            #pragma unroll
            for (int nt = 0; nt < 8; nt++)
                *(float2*)(out + nt * 8 + tig * 2) =
                    make_float2(acc[mt][nt][2 * half], acc[mt][nt][2 * half + 1]);
        }
}

// ---------------- utility kernels ----------------
__global__ void zero_z_kernel() { g_Z[blockIdx.x * 256 + threadIdx.x] = 0.0f; }
__global__ void recip_z_kernel() {
    int i = blockIdx.x * 256 + threadIdx.x;
    g_invZ[i] = 1.0f / g_Z[i];
}

extern "C" void kernel_launch(void* const* d_in, const int* in_sizes, int n_in,
                              void* d_out, int out_size) {
    const float* q    = (const float*)d_in[0];
    const float* k    = (const float*)d_in[1];
    const float* v    = (const float*)d_in[2];
    const float* w_q  = (const float*)d_in[3];
    const float* w_k  = (const float*)d_in[4];
    const float* w_v  = (const float*)d_in[5];
    const float* fc_y = (const float*)d_in[6];

    float* y    = (float*)d_out;
    float* attn = (float*)d_out + Y_ELEMS;

    zero_z_kernel<<<(BATCH * H * L) / 256, 256>>>();

    // 1. all three projections in one launch -> head-major scratch
    dim3 gproj(8, 32, 3);                     // (n-tile, m-tile, which)
    proj_kernel<<<gproj, 128>>>(q, k, v, w_q, w_k, w_v);

    // 2. S = QK^T/sqrt(LK); attnU = exp(S); Z += rowsums
    dim3 gqk(16, 16, 32);                     // (n-tile, m-tile, bh)
    qk_kernel<<<gqk, 128>>>(attn);

    recip_z_kernel<<<(BATCH * H * L) / 256, 256>>>();

    // 3. yh = attn @ V with fused attn normalization writeback
    dim3 gpv(8, 32);                          // (m-tile 256, bh)
    pv_kernel<<<gpv, 128>>>(attn);

    // 4. y = yh @ fc_y^T
    dim3 gfin(8, 32);                         // (n-tile, m-tile)
    final_kernel<<<gfin, 128>>>(fc_y, y);
}

// round 15
// speedup vs baseline: 1.0592x; 1.0592x over previous
#include <cuda_runtime.h>
#include <cstdint>
#include <math.h>

// ---------------- problem constants ----------------
constexpr int BATCH = 2;
constexpr int H     = 16;
constexpr int L     = 2048;
constexpr int D     = 64;
constexpr int C     = 1024;
constexpr long Y_ELEMS = (long)BATCH * L * C;
constexpr float QK_SCALE = 0.022097086912079608f;   // 1/sqrt(2048)

#define SST 36   // smem row stride (floats): 16B-aligned rows (144B), conflict-free

// ---------------- scratch ----------------
__device__ float g_qh[(long)BATCH * H * L * D];   // [bh][l][d]
__device__ float g_kh[(long)BATCH * H * L * D];   // [bh][l][d]
__device__ float g_vt[(long)BATCH * H * D * L];   // [bh][d][l]  (V transposed)
__device__ float g_yh[(long)BATCH * L * H * D];   // [b][l][h*64+d]
__device__ float g_Z[BATCH * H * L];

// ---------------- helpers ----------------
__device__ __forceinline__ uint32_t smem_u32(const void* p) {
    uint32_t a;
    asm("{ .reg .u64 t; cvta.to.shared.u64 t, %1; cvt.u32.u64 %0, t; }" : "=r"(a) : "l"(p));
    return a;
}
__device__ __forceinline__ uint32_t f2tf(float f) {
    uint32_t r;
    asm("cvt.rna.tf32.f32 %0, %1;" : "=r"(r) : "f"(f));
    return r;
}
__device__ __forceinline__ void mma8(float* c, const uint32_t* a, const uint32_t* b) {
    asm volatile("mma.sync.aligned.m16n8k8.row.col.f32.tf32.tf32.f32 "
        "{%0,%1,%2,%3}, {%4,%5,%6,%7}, {%8,%9}, {%0,%1,%2,%3};"
        : "+f"(c[0]), "+f"(c[1]), "+f"(c[2]), "+f"(c[3])
        : "r"(a[0]), "r"(a[1]), "r"(a[2]), "r"(a[3]), "r"(b[0]), "r"(b[1]));
}
// ldmatrix x4: four 8x8 b16 tiles == four 8x4 tf32 tiles (bit-identical layout)
__device__ __forceinline__ void ldm4(uint32_t* r, uint32_t saddr) {
    asm volatile("ldmatrix.sync.aligned.m8n8.x4.shared.b16 {%0,%1,%2,%3}, [%4];"
        : "=r"(r[0]), "=r"(r[1]), "=r"(r[2]), "=r"(r[3]) : "r"(saddr));
}

// ---------------- GEMM core v9 (R12, proven): single-buffer BK=32, ldmatrix ----------------
// D[BM x BN] = A[BM x K] * B[BN x K]^T, fp32 gmem (K contiguous), tf32 MMA.
// 128 threads = 4 warps, warp tile 64x64, warp grid WM x (4/WM), BK=32,
// per-iter: LDG->regs, sync, cvt+STS, sync, MMA (ldmatrix fragment loads).
// acc[mt][nt][4]: row = wm+mt*16+group (+8), col = wn+nt*8+tig*2 (+1).
// WB: after compute, scale the consumed A chunk by invz[row], write to wb_out.
template<int BM_, int BN_, int WM_, bool WB>
__device__ __forceinline__ void gemm9(const float* __restrict__ A, long lda,
                                      const float* __restrict__ Bp, long ldb,
                                      int niter, float acc[4][8][4],
                                      uint32_t* __restrict__ As, uint32_t* __restrict__ Bs,
                                      float* __restrict__ wb_out, long wb_ld,
                                      const float* __restrict__ invz) {
    constexpr int NA = BM_ / 16, NB = BN_ / 16;
    const int tid = threadIdx.x;
    const int lane = tid & 31, wid = tid >> 5;
    const int wm = (wid % WM_) * 64, wn = (wid / WM_) * 64;

    const uint32_t aB = smem_u32(As), bB = smem_u32(Bs);
    uint32_t aAdr[4], bAdr[4];
    {
        const int arow = lane & 15, akadd = (lane >> 4) * 4;
        #pragma unroll
        for (int mt = 0; mt < 4; mt++)
            aAdr[mt] = aB + (uint32_t)(((wm + mt * 16 + arow) * SST + akadd) * 4);
        const int brow = ((lane >> 4) & 1) * 8 + (lane & 7);
        const int bkadd = ((lane >> 3) & 1) * 4;
        #pragma unroll
        for (int p = 0; p < 4; p++)
            bAdr[p] = bB + (uint32_t)(((wn + p * 16 + brow) * SST + bkadd) * 4);
    }

    for (int it = 0; it < niter; it++) {
        const long k0 = (long)it * 32;
        float4 av[NA], bv[NB];
        #pragma unroll
        for (int i = 0; i < NA; i++) {
            int c = tid + i * 128, r = c >> 3, q = (c & 7) * 4;
            av[i] = *(const float4*)(A + (long)r * lda + k0 + q);
        }
        #pragma unroll
        for (int i = 0; i < NB; i++) {
            int c = tid + i * 128, r = c >> 3, q = (c & 7) * 4;
            bv[i] = *(const float4*)(Bp + (long)r * ldb + k0 + q);
        }
        __syncthreads();   // previous iteration fully consumed (incl. WB)
        #pragma unroll
        for (int i = 0; i < NA; i++) {
            int c = tid + i * 128, r = c >> 3, q = (c & 7) * 4;
            *(uint4*)&As[r * SST + q] =
                make_uint4(f2tf(av[i].x), f2tf(av[i].y), f2tf(av[i].z), f2tf(av[i].w));
        }
        #pragma unroll
        for (int i = 0; i < NB; i++) {
            int c = tid + i * 128, r = c >> 3, q = (c & 7) * 4;
            *(uint4*)&Bs[r * SST + q] =
                make_uint4(f2tf(bv[i].x), f2tf(bv[i].y), f2tf(bv[i].z), f2tf(bv[i].w));
        }
        __syncthreads();

        #pragma unroll
        for (int ks = 0; ks < 4; ks++) {
            uint32_t af[4][4], bf[4][4];
            #pragma unroll
            for (int mt = 0; mt < 4; mt++) ldm4(af[mt], aAdr[mt] + ks * 32);
            #pragma unroll
            for (int p = 0; p < 4; p++) ldm4(bf[p], bAdr[p] + ks * 32);
            #pragma unroll
            for (int mt = 0; mt < 4; mt++)
                #pragma unroll
                for (int p = 0; p < 4; p++) {
                    mma8(acc[mt][2 * p],     af[mt], &bf[p][0]);
                    mma8(acc[mt][2 * p + 1], af[mt], &bf[p][2]);
                }
        }

        if (WB) {   // fused normalization writeback of the consumed A chunk
            #pragma unroll
            for (int i = 0; i < NA; i++) {
                int c = tid + i * 128, r = c >> 3, q = (c & 7) * 4;
                const uint32_t* p = &As[r * SST + q];
                const float s = invz[r];
                *(float4*)(wb_out + (long)r * wb_ld + k0 + q) =
                    make_float4(__uint_as_float(p[0]) * s, __uint_as_float(p[1]) * s,
                                __uint_as_float(p[2]) * s, __uint_as_float(p[3]) * s);
            }
        }
    }
}

// ---------------- kernels ----------------
// merged projections: z=0 -> qh, z=1 -> kh, z=2 -> vt (transposed via smem)
__global__ void __launch_bounds__(128) proj_kernel(const float* __restrict__ q,
                                                   const float* __restrict__ k,
                                                   const float* __restrict__ v,
                                                   const float* __restrict__ wq,
                                                   const float* __restrict__ wk,
                                                   const float* __restrict__ wv) {
    __shared__ uint32_t sm[2 * 128 * SST];        // As | Bs, reused as transpose buffer
    const int which = blockIdx.z;
    const float* X = (which == 0) ? q : (which == 1) ? k : v;
    const float* W = (which == 0) ? wq : (which == 1) ? wk : wv;

    float acc[4][8][4] = {};
    const int m0 = blockIdx.y * 128, n0 = blockIdx.x * 128;
    gemm9<128, 128, 2, false>(X + (long)m0 * C, C, W + (long)n0 * C, C, C / 32, acc,
                              sm, sm + 128 * SST, nullptr, 0, nullptr);

    const int tid = threadIdx.x;
    const int lane = tid & 31, wid = tid >> 5;
    const int wm = (wid % 2) * 64, wn = (wid / 2) * 64;
    const int group = lane >> 2, tig = lane & 3;

    if (which == 2) {
        // transpose through smem: [n_local][m] tile (64 rows per pass), pad 132
        float* tb = (float*)sm;                   // 64*132 floats = 33.8KB <= 36.8KB
        const int b = m0 >> 11, l0 = m0 & 2047;   // whole CTA in one batch
        #pragma unroll
        for (int p = 0; p < 2; p++) {
            __syncthreads();                      // prior tb reads / MMA smem reads done
            if ((wid >> 1) == p) {                // warps owning n in [p*64, p*64+64)
                #pragma unroll
                for (int mt = 0; mt < 4; mt++)
                    #pragma unroll
                    for (int nt = 0; nt < 8; nt++) {
                        const int nl = nt * 8 + tig * 2;          // wn - p*64 == 0
                        const int mr = wm + mt * 16 + group;
                        tb[nl * 132 + mr]           = acc[mt][nt][0];
                        tb[(nl + 1) * 132 + mr]     = acc[mt][nt][1];
                        tb[nl * 132 + mr + 8]       = acc[mt][nt][2];
                        tb[(nl + 1) * 132 + mr + 8] = acc[mt][nt][3];
                    }
            }
            __syncthreads();
            // coalesced stores: 64 rows x 128 l-values
            #pragma unroll
            for (int i = 0; i < 16; i++) {
                int c = tid + i * 128;            // 0..2047
                int row = c >> 5, cg = (c & 31) * 4;
                int n = n0 + p * 64 + row;
                int h = n >> 6, d = n & 63;
                float4 val = *(float4*)&tb[row * 132 + cg];
                *(float4*)(g_vt + (long)(b * H + h) * D * L + (long)d * L + l0 + cg) = val;
            }
        }
    } else {
        float* base = (which == 0) ? g_qh : g_kh;
        #pragma unroll
        for (int mt = 0; mt < 4; mt++)
            #pragma unroll
            for (int half = 0; half < 2; half++) {
                const int m = m0 + wm + mt * 16 + group + 8 * half;
                const int b = m >> 11, l = m & 2047;
                #pragma unroll
                for (int nt = 0; nt < 8; nt++) {
                    const int n = n0 + wn + nt * 8 + tig * 2;
                    const int h = n >> 6, d = n & 63;
                    *(float2*)(base + ((long)(b * H + h) * L + l) * D + d) =
                        make_float2(acc[mt][nt][2 * half], acc[mt][nt][2 * half + 1]);
                }
            }
    }
}

// QK^T -> exp -> unnormalized attn + row-sum atomics
__global__ void __launch_bounds__(128) qk_kernel(float* __restrict__ attnU) {
    __shared__ uint32_t As[128 * SST], Bs[128 * SST];
    float acc[4][8][4] = {};
    const int n0 = blockIdx.x * 128, m0 = blockIdx.y * 128, bh = blockIdx.z;
    gemm9<128, 128, 2, false>(g_qh + ((long)bh * L + m0) * D, D,
                              g_kh + ((long)bh * L + n0) * D, D, 2, acc,
                              As, Bs, nullptr, 0, nullptr);

    const int lane = threadIdx.x & 31, wid = threadIdx.x >> 5;
    const int wm = (wid % 2) * 64, wn = (wid / 2) * 64;
    const int group = lane >> 2, tig = lane & 3;
    float* outbase = attnU + (long)bh * L * L;
    #pragma unroll
    for (int mt = 0; mt < 4; mt++)
        #pragma unroll
        for (int half = 0; half < 2; half++) {
            const int row = m0 + wm + mt * 16 + group + 8 * half;
            float* outr = outbase + (long)row * L + n0 + wn;
            float sum = 0.0f;
            #pragma unroll
            for (int nt = 0; nt < 8; nt++) {
                float e0 = __expf(acc[mt][nt][2 * half] * QK_SCALE);
                float e1 = __expf(acc[mt][nt][2 * half + 1] * QK_SCALE);
                sum += e0 + e1;
                *(float2*)(outr + nt * 8 + tig * 2) = make_float2(e0, e1);
            }
            sum += __shfl_xor_sync(0xFFFFFFFF, sum, 1);
            sum += __shfl_xor_sync(0xFFFFFFFF, sum, 2);
            if (tig == 0) atomicAdd(&g_Z[bh * L + row], sum);
        }
}

// PV with fused normalization: reads unnormalized attn, writes normalized attn
// in place + scaled yh.  invz computed inline from g_Z (recip kernel folded in).
__global__ void __launch_bounds__(128) pv_kernel(float* __restrict__ attn) {
    __shared__ uint32_t As[256 * SST], Bs[64 * SST];
    __shared__ float invz_s[256];
    const int m0 = blockIdx.x * 256, bh = blockIdx.y;
    for (int i = threadIdx.x; i < 256; i += 128)
        invz_s[i] = 1.0f / g_Z[bh * L + m0 + i];
    __syncthreads();

    float acc[4][8][4] = {};
    float* arow = attn + (long)bh * L * L + (long)m0 * L;
    gemm9<256, 64, 4, true>(arow, L, g_vt + (long)bh * D * L, L, L / 32, acc,
                            As, Bs, arow, L, invz_s);

    const int lane = threadIdx.x & 31, wid = threadIdx.x >> 5;
    const int wm = wid * 64;
    const int group = lane >> 2, tig = lane & 3;
    const int b = bh >> 4, hh = bh & 15;
    #pragma unroll
    for (int mt = 0; mt < 4; mt++)
        #pragma unroll
        for (int half = 0; half < 2; half++) {
            const int rl = wm + mt * 16 + group + 8 * half;
            const float s = invz_s[rl];
            float* out = g_yh + (long)(b * L + m0 + rl) * C + hh * 64;
            #pragma unroll
            for (int nt = 0; nt < 8; nt++)
                *(float2*)(out + nt * 8 + tig * 2) =
                    make_float2(acc[mt][nt][2 * half] * s, acc[mt][nt][2 * half + 1] * s);
        }
}

// y = yh @ fc_y^T
__global__ void __launch_bounds__(128) final_kernel(const float* __restrict__ Wf,
                                                    float* __restrict__ Y) {
    __shared__ uint32_t As[128 * SST], Bs[128 * SST];
    float acc[4][8][4] = {};
    const int n0 = blockIdx.x * 128, m0 = blockIdx.y * 128;
    gemm9<128, 128, 2, false>(g_yh + (long)m0 * C, C, Wf + (long)n0 * C, C, C / 32, acc,
                              As, Bs, nullptr, 0, nullptr);

    const int lane = threadIdx.x & 31, wid = threadIdx.x >> 5;
    const int wm = (wid % 2) * 64, wn = (wid / 2) * 64;
    const int group = lane >> 2, tig = lane & 3;
    #pragma unroll
    for (int mt = 0; mt < 4; mt++)
        #pragma unroll
        for (int half = 0; half < 2; half++) {
            const int row = m0 + wm + mt * 16 + group + 8 * half;
            float* out = Y + (long)row * C + n0 + wn;
            #pragma unroll
            for (int nt = 0; nt < 8; nt++)
                *(float2*)(out + nt * 8 + tig * 2) =
                    make_float2(acc[mt][nt][2 * half], acc[mt][nt][2 * half + 1]);
        }
}

// ---------------- utility kernels ----------------
__global__ void zero_z_kernel() { g_Z[blockIdx.x * 256 + threadIdx.x] = 0.0f; }

extern "C" void kernel_launch(void* const* d_in, const int* in_sizes, int n_in,
                              void* d_out, int out_size) {
    const float* q    = (const float*)d_in[0];
    const float* k    = (const float*)d_in[1];
    const float* v    = (const float*)d_in[2];
    const float* w_q  = (const float*)d_in[3];
    const float* w_k  = (const float*)d_in[4];
    const float* w_v  = (const float*)d_in[5];
    const float* fc_y = (const float*)d_in[6];

    float* y    = (float*)d_out;
    float* attn = (float*)d_out + Y_ELEMS;

    zero_z_kernel<<<(BATCH * H * L) / 256, 256>>>();

    // 1. all three projections in one launch -> head-major scratch
    dim3 gproj(8, 32, 3);                     // (n-tile, m-tile, which)
    proj_kernel<<<gproj, 128>>>(q, k, v, w_q, w_k, w_v);

    // 2. S = QK^T/sqrt(LK); attnU = exp(S); Z += rowsums
    dim3 gqk(16, 16, 32);                     // (n-tile, m-tile, bh)
    qk_kernel<<<gqk, 128>>>(attn);

    // 3. yh = attn @ V with fused attn normalization writeback (invz inline)
    dim3 gpv(8, 32);                          // (m-tile 256, bh)
    pv_kernel<<<gpv, 128>>>(attn);

    // 4. y = yh @ fc_y^T
    dim3 gfin(8, 32);                         // (n-tile, m-tile)
    final_kernel<<<gfin, 128>>>(fc_y, y);
}